// round 2
// baseline (speedup 1.0000x reference)
#include <cuda_runtime.h>
#include <cuda_bf16.h>

// Problem constants
#define NN 200000
#define EE 600000
#define GG 8192
#define HH 128
#define DIN 30

typedef unsigned long long u64;

// ---------------- scratch (device globals; no allocations allowed) ----------
__device__ float g_act[(size_t)NN * 32];   // layer-1 padded x, stride 32
__device__ float g_h[(size_t)NN * HH];     // h = act @ W
__device__ float g_agg[(size_t)NN * HH];   // aggregation buffer
__device__ float g_dinv[NN];               // deg -> rsqrt(deg)
__device__ float g_invcnt[GG];             // counts -> 1/max(count,1)

// ---------------- init: zero output, deg=1 (self loop), counts=0 ------------
__global__ void init_kernel(float* __restrict__ out) {
    int idx = blockIdx.x * blockDim.x + threadIdx.x;
    if (idx < GG * HH) out[idx] = 0.0f;
    if (idx < NN) g_dinv[idx] = 1.0f;
    if (idx < GG) g_invcnt[idx] = 0.0f;
}

// ---------------- degree + batch counts -------------------------------------
__global__ void count_kernel(const int* __restrict__ dst, const int* __restrict__ batch_idx) {
    int idx = blockIdx.x * blockDim.x + threadIdx.x;
    if (idx < EE) atomicAdd(&g_dinv[dst[idx]], 1.0f);
    if (idx < NN) atomicAdd(&g_invcnt[batch_idx[idx]], 1.0f);
}

__global__ void finalize_kernel() {
    int idx = blockIdx.x * blockDim.x + threadIdx.x;
    if (idx < NN) g_dinv[idx] = rsqrtf(g_dinv[idx]);
    if (idx < GG) g_invcnt[idx] = 1.0f / fmaxf(g_invcnt[idx], 1.0f);
}

// ---------------- pad x [N,30] -> g_act [N,32] ------------------------------
__global__ void pad_x_kernel(const float* __restrict__ x) {
    int idx = blockIdx.x * blockDim.x + threadIdx.x;   // over N*32
    if (idx >= NN * 32) return;
    int n = idx >> 5;
    int k = idx & 31;
    g_act[idx] = (k < DIN) ? x[n * DIN + k] : 0.0f;
}

// ---------------- packed-pair helpers ---------------------------------------
__device__ __forceinline__ u64 dup_f32(float v) {
    u64 p;
    asm("mov.b64 %0, {%1, %1};" : "=l"(p) : "f"(v));
    return p;
}
__device__ __forceinline__ void ffma2(u64& acc, u64 a, u64 b) {
    asm("fma.rn.f32x2 %0, %1, %2, %0;" : "+l"(acc) : "l"(a), "l"(b));
}
__device__ __forceinline__ float2 unpack_f32x2(u64 p) {
    float lo, hi;
    asm("mov.b64 {%0, %1}, %2;" : "=f"(lo), "=f"(hi) : "l"(p));
    return make_float2(lo, hi);
}

// ---------------- GEMM: h = relu_in(act) @ W ; agg = h * dinv^2 -------------
// 256 threads/block, tile = 64 nodes x 128 cols, 8 rows x 4 cols per thread.
// Inner loop uses packed fma.rn.f32x2 (2 MACs per fma-pipe slot).
// If FUSE != 0, the X operand is relu(in + bias) computed during staging.
template <int KPAD, int KW, int FUSE>
__global__ void __launch_bounds__(256) gemm_kernel(const float* __restrict__ in,
                                                   const float* __restrict__ W,
                                                   const float* __restrict__ bias,
                                                   float* __restrict__ h,
                                                   float* __restrict__ agg) {
    constexpr int KB = 32;
    __shared__ float Ws[KB][HH];      // 16 KB
    __shared__ u64   Xs2[64][KB];     // 16 KB, each entry = (x,x) packed pair

    const int tid   = threadIdx.x;
    const int col   = (tid & 31) * 4;     // 4 contiguous cols per lane
    const int rb    = tid >> 5;           // row base 0..7
    const int node0 = blockIdx.x * 64;

    u64 acc2[8][2];
#pragma unroll
    for (int i = 0; i < 8; i++) { acc2[i][0] = 0ULL; acc2[i][1] = 0ULL; }

    for (int k0 = 0; k0 < KPAD; k0 += KB) {
        // ---- stage W chunk [KB x 128] (zero-pad rows >= KW)
#pragma unroll
        for (int i = 0; i < 4; i++) {
            int j  = tid + 256 * i;       // float4 index 0..1023
            int kr = j >> 5;              // chunk row
            int cc = (j & 31) * 4;
            int kg = k0 + kr;
            float4 wv = make_float4(0.f, 0.f, 0.f, 0.f);
            if (kg < KW) wv = *(const float4*)&W[kg * HH + cc];
            *(float4*)&Ws[kr][cc] = wv;
        }
        // ---- stage X chunk [64 x KB] as duplicated pairs, fusing relu+bias
#pragma unroll
        for (int i = 0; i < 2; i++) {
            int j  = tid + 256 * i;       // float4 index 0..511
            int r  = j >> 3;
            int c4 = (j & 7) * 4;
            float4 v = *(const float4*)&in[(size_t)(node0 + r) * KPAD + k0 + c4];
            if (FUSE) {
                float4 b = __ldg((const float4*)&bias[k0 + c4]);
                v.x = fmaxf(v.x + b.x, 0.f);
                v.y = fmaxf(v.y + b.y, 0.f);
                v.z = fmaxf(v.z + b.z, 0.f);
                v.w = fmaxf(v.w + b.w, 0.f);
            }
            ulonglong2 s0, s1;
            s0.x = dup_f32(v.x); s0.y = dup_f32(v.y);
            s1.x = dup_f32(v.z); s1.y = dup_f32(v.w);
            *(ulonglong2*)&Xs2[r][c4]     = s0;
            *(ulonglong2*)&Xs2[r][c4 + 2] = s1;
        }
        __syncthreads();
#pragma unroll
        for (int kk = 0; kk < KB; kk++) {
            ulonglong2 wv = *(const ulonglong2*)&Ws[kk][col];   // (w0,w1),(w2,w3)
#pragma unroll
            for (int i = 0; i < 8; i++) {
                u64 xv = Xs2[rb + 8 * i][kk];                   // broadcast LDS.64
                ffma2(acc2[i][0], xv, wv.x);
                ffma2(acc2[i][1], xv, wv.y);
            }
        }
        __syncthreads();
    }
#pragma unroll
    for (int i = 0; i < 8; i++) {
        int n = node0 + rb + 8 * i;
        float dv = g_dinv[n];
        float d2 = dv * dv;
        float2 p0 = unpack_f32x2(acc2[i][0]);
        float2 p1 = unpack_f32x2(acc2[i][1]);
        float4 hv = make_float4(p0.x, p0.y, p1.x, p1.y);
        *(float4*)&h[(size_t)n * HH + col] = hv;
        float4 av = make_float4(hv.x * d2, hv.y * d2, hv.z * d2, hv.w * d2);
        *(float4*)&agg[(size_t)n * HH + col] = av;
    }
}

// ---------------- edge scatter: agg[dst] += h[src] * dinv[s]*dinv[d] --------
// one warp per edge; each lane handles 4 floats; vector L2 reduction.
__global__ void __launch_bounds__(256) scatter_kernel(const int* __restrict__ src,
                                                      const int* __restrict__ dst) {
    int e = blockIdx.x * 8 + (threadIdx.x >> 5);
    if (e >= EE) return;
    int lane = threadIdx.x & 31;
    int s = __ldg(&src[e]);
    int d = __ldg(&dst[e]);
    float w = g_dinv[s] * g_dinv[d];
    float4 v = *(const float4*)&g_h[(size_t)s * HH + lane * 4];
    float4 m = make_float4(v.x * w, v.y * w, v.z * w, v.w * w);
    float* p = &g_agg[(size_t)d * HH + lane * 4];
    asm volatile("red.global.add.v4.f32 [%0], {%1, %2, %3, %4};"
                 :: "l"(p), "f"(m.x), "f"(m.y), "f"(m.z), "f"(m.w)
                 : "memory");
}

// ---------------- final: relu + bias + mean-pool into out -------------------
__global__ void epilogue_pool_kernel(const float* __restrict__ bias,
                                     const int* __restrict__ batch_idx,
                                     float* __restrict__ out) {
    int idx = blockIdx.x * blockDim.x + threadIdx.x;   // over N*32
    if (idx >= NN * 32) return;
    int n  = idx >> 5;
    int c4 = (idx & 31) * 4;
    int g  = __ldg(&batch_idx[n]);
    float w = g_invcnt[g];
    float4 a = *(const float4*)&g_agg[(size_t)n * HH + c4];
    float4 b = *(const float4*)&bias[c4];
    float4 r = make_float4(fmaxf(a.x + b.x, 0.f) * w, fmaxf(a.y + b.y, 0.f) * w,
                           fmaxf(a.z + b.z, 0.f) * w, fmaxf(a.w + b.w, 0.f) * w);
    float* p = &out[(size_t)g * HH + c4];
    asm volatile("red.global.add.v4.f32 [%0], {%1, %2, %3, %4};"
                 :: "l"(p), "f"(r.x), "f"(r.y), "f"(r.z), "f"(r.w)
                 : "memory");
}

// ---------------- launch ------------------------------------------------------
extern "C" void kernel_launch(void* const* d_in, const int* in_sizes, int n_in,
                              void* d_out, int out_size) {
    const float* x         = (const float*)d_in[0];
    const int*   edge      = (const int*)d_in[1];     // [2, E]
    const int*   batch_idx = (const int*)d_in[2];
    const float* W1        = (const float*)d_in[3];
    const float* b1        = (const float*)d_in[4];
    const float* W2        = (const float*)d_in[5];
    const float* b2        = (const float*)d_in[6];
    const float* W3        = (const float*)d_in[7];
    const float* b3        = (const float*)d_in[8];
    float* out = (float*)d_out;

    const int* src = edge;
    const int* dst = edge + EE;

    float *h, *agg, *act;
    cudaGetSymbolAddress((void**)&h,   g_h);
    cudaGetSymbolAddress((void**)&agg, g_agg);
    cudaGetSymbolAddress((void**)&act, g_act);

    const int T = 256;
    init_kernel<<<(GG * HH + T - 1) / T, T>>>(out);
    count_kernel<<<(EE + T - 1) / T, T>>>(dst, batch_idx);
    finalize_kernel<<<(NN + T - 1) / T, T>>>();
    pad_x_kernel<<<(NN * 32 + T - 1) / T, T>>>(x);

    const int gemm_grid    = NN / 64;            // 3125
    const int scatter_grid = (EE + 7) / 8;       // 75000
    const int vec_grid     = (NN * 32 + T - 1) / T;

    // ---- layer 1 (K=30 padded to 32; X already relu-free raw input)
    gemm_kernel<32, DIN, 0><<<gemm_grid, T>>>(act, W1, nullptr, h, agg);
    scatter_kernel<<<scatter_grid, T>>>(src, dst);

    // ---- layer 2: X = relu(agg + b1) fused into GEMM staging
    gemm_kernel<HH, HH, 1><<<gemm_grid, T>>>(agg, W2, b1, h, agg);
    scatter_kernel<<<scatter_grid, T>>>(src, dst);

    // ---- layer 3: X = relu(agg + b2) fused into GEMM staging
    gemm_kernel<HH, HH, 1><<<gemm_grid, T>>>(agg, W3, b2, h, agg);
    scatter_kernel<<<scatter_grid, T>>>(src, dst);

    // ---- final: relu + b3 + mean-pool
    epilogue_pool_kernel<<<vec_grid, T>>>(b3, batch_idx, out);
}

// round 4
// speedup vs baseline: 1.1594x; 1.1594x over previous
#include <cuda_runtime.h>
#include <cuda_bf16.h>
#include <cstdint>

// Problem constants
#define NN 200000
#define NPAD 200064          // 1563 * 128
#define EE 600000
#define GG 8192
#define HH 128
#define DIN 30

typedef unsigned long long u64;
typedef unsigned int u32;

// ---------------- scratch (device globals; no allocations allowed) ----------
__device__ __nv_bfloat16 g_x1h[(size_t)NPAD * 32];   // layer1 input hi (K padded to 32)
__device__ __nv_bfloat16 g_x1l[(size_t)NPAD * 32];   // layer1 input lo
__device__ __nv_bfloat16 g_w1h[128 * 32],  g_w1l[128 * 32];    // W1^T split [n][k], k padded 32
__device__ __nv_bfloat16 g_w2h[128 * 128], g_w2l[128 * 128];   // W2^T split
__device__ __nv_bfloat16 g_w3h[128 * 128], g_w3l[128 * 128];   // W3^T split
__device__ float g_h[(size_t)NPAD * HH];    // h = act @ W
__device__ float g_agg[(size_t)NPAD * HH];  // aggregation buffer
__device__ float g_dinv[NN];                // deg -> rsqrt(deg)
__device__ float g_invcnt[GG];              // counts -> 1/max(count,1)

// ---------------- split helpers ----------------------------------------------
__device__ __forceinline__ u32 pack2(__nv_bfloat16 a, __nv_bfloat16 b) {
    return (u32)__bfloat16_as_ushort(a) | ((u32)__bfloat16_as_ushort(b) << 16);
}
__device__ __forceinline__ void split8(const float* v, uint4& hi, uint4& lo) {
    __nv_bfloat16 h[8];
    float r[8];
#pragma unroll
    for (int i = 0; i < 8; i++) { h[i] = __float2bfloat16(v[i]); r[i] = v[i] - __bfloat162float(h[i]); }
    hi.x = pack2(h[0], h[1]); hi.y = pack2(h[2], h[3]);
    hi.z = pack2(h[4], h[5]); hi.w = pack2(h[6], h[7]);
    lo.x = pack2(__float2bfloat16(r[0]), __float2bfloat16(r[1]));
    lo.y = pack2(__float2bfloat16(r[2]), __float2bfloat16(r[3]));
    lo.z = pack2(__float2bfloat16(r[4]), __float2bfloat16(r[5]));
    lo.w = pack2(__float2bfloat16(r[6]), __float2bfloat16(r[7]));
}

// bf16 HMMA m16n8k16, fp32 accumulate (portable sm_80+ path)
__device__ __forceinline__ void mma16816(float* c, const u32* a, const u32* b) {
    asm volatile(
        "mma.sync.aligned.m16n8k16.row.col.f32.bf16.bf16.f32 "
        "{%0,%1,%2,%3}, {%4,%5,%6,%7}, {%8,%9}, {%0,%1,%2,%3};"
        : "+f"(c[0]), "+f"(c[1]), "+f"(c[2]), "+f"(c[3])
        : "r"(a[0]), "r"(a[1]), "r"(a[2]), "r"(a[3]), "r"(b[0]), "r"(b[1]));
}

// ---------------- setup kernels ----------------------------------------------
__global__ void init_kernel(float* __restrict__ out) {
    int idx = blockIdx.x * blockDim.x + threadIdx.x;
    if (idx < GG * HH) out[idx] = 0.0f;
    if (idx < NN) g_dinv[idx] = 1.0f;
    if (idx < GG) g_invcnt[idx] = 0.0f;
}

__global__ void count_kernel(const int* __restrict__ dst, const int* __restrict__ batch_idx) {
    int idx = blockIdx.x * blockDim.x + threadIdx.x;
    if (idx < EE) atomicAdd(&g_dinv[dst[idx]], 1.0f);
    if (idx < NN) atomicAdd(&g_invcnt[batch_idx[idx]], 1.0f);
}

__global__ void finalize_kernel() {
    int idx = blockIdx.x * blockDim.x + threadIdx.x;
    if (idx < NN) g_dinv[idx] = rsqrtf(g_dinv[idx]);
    if (idx < GG) g_invcnt[idx] = 1.0f / fmaxf(g_invcnt[idx], 1.0f);
}

// pad x [N,30] -> split bf16 hi/lo [NPAD,32]
__global__ void splitx_kernel(const float* __restrict__ x) {
    int idx = blockIdx.x * blockDim.x + threadIdx.x;   // over NPAD*4 8-elem units
    if (idx >= NPAD * 4) return;
    int n = idx >> 2;
    int cu = idx & 3;
    float v[8];
#pragma unroll
    for (int j = 0; j < 8; j++) {
        int k = cu * 8 + j;
        v[j] = (n < NN && k < DIN) ? x[(size_t)n * DIN + k] : 0.0f;
    }
    uint4 hi, lo;
    split8(v, hi, lo);
    *(uint4*)&g_x1h[(size_t)n * 32 + cu * 8] = hi;
    *(uint4*)&g_x1l[(size_t)n * 32 + cu * 8] = lo;
}

// transpose + split W [K,128] -> Wt hi/lo [128, KT]
__global__ void prepw_kernel(const float* __restrict__ W, int K, int KT,
                             __nv_bfloat16* __restrict__ wh, __nv_bfloat16* __restrict__ wl) {
    int idx = blockIdx.x * blockDim.x + threadIdx.x;
    if (idx >= 128 * KT) return;
    int c = idx / KT, k = idx % KT;
    float v = (k < K) ? W[(size_t)k * HH + c] : 0.0f;
    __nv_bfloat16 h = __float2bfloat16(v);
    wh[idx] = h;
    wl[idx] = __float2bfloat16(v - __bfloat162float(h));
}

// ---------------- tensor-core GEMM (mma.sync bf16, split precision) ---------
// D[128,128] = A[128,KT] @ Wt[128,KT]^T via AhWh + AhWl + AlWh.
// FUSE=1: A = relu(inf + bias) split on the fly; else pre-split bf16 (inh/inl).
// Epilogue: h = D ; agg = D * dinv^2.
template <int KT, int FUSE>
__global__ void __launch_bounds__(256) gemm_mma(
    const __nv_bfloat16* __restrict__ inh, const __nv_bfloat16* __restrict__ inl,
    const float* __restrict__ inf, const float* __restrict__ bias,
    const __nv_bfloat16* __restrict__ wh, const __nv_bfloat16* __restrict__ wl,
    float* __restrict__ hout, float* __restrict__ agg)
{
    constexpr int KC = (KT < 64) ? KT : 64;   // k-chunk
    constexpr int SP = KC + 8;                // padded smem stride (elements)
    constexpr int UNITS = 128 * (KC / 8);     // 8-elem staging units per array

    extern __shared__ __nv_bfloat16 sm[];
    __nv_bfloat16* Ah = sm;
    __nv_bfloat16* Al = sm + 128 * SP;
    __nv_bfloat16* Wh = sm + 2 * 128 * SP;
    __nv_bfloat16* Wl = sm + 3 * 128 * SP;

    const int tid   = threadIdx.x;
    const int w     = tid >> 5;
    const int lane  = tid & 31;
    const int mrow  = (w & 3) * 32;           // warp row base in tile
    const int ncol  = (w >> 2) * 64;          // warp col base in tile
    const int node0 = blockIdx.x * 128;

    float acc[2][8][4];
#pragma unroll
    for (int mt = 0; mt < 2; mt++)
#pragma unroll
        for (int nt = 0; nt < 8; nt++)
#pragma unroll
            for (int i = 0; i < 4; i++) acc[mt][nt][i] = 0.f;

    for (int c = 0; c < KT / KC; c++) {
        const int k0 = c * KC;
        if (c) __syncthreads();
        // ---- stage W chunk [128 n][KC k]
        for (int u = tid; u < UNITS; u += 256) {
            int row = u / (KC / 8);
            int cu  = u % (KC / 8);
            uint4 vh = *(const uint4*)&wh[(size_t)row * KT + k0 + cu * 8];
            uint4 vl = *(const uint4*)&wl[(size_t)row * KT + k0 + cu * 8];
            *(uint4*)&Wh[row * SP + cu * 8] = vh;
            *(uint4*)&Wl[row * SP + cu * 8] = vl;
        }
        // ---- stage A chunk [128 m][KC k] with optional relu+bias+split fusion
        for (int u = tid; u < UNITS; u += 256) {
            int row = u / (KC / 8);
            int cu  = u % (KC / 8);
            uint4 vh, vl;
            if (FUSE) {
                const float* s = inf + (size_t)(node0 + row) * HH + k0 + cu * 8;
                float4 a0 = *(const float4*)s;
                float4 a1 = *(const float4*)(s + 4);
                float4 b0 = *(const float4*)&bias[k0 + cu * 8];
                float4 b1 = *(const float4*)&bias[k0 + cu * 8 + 4];
                float v[8];
                v[0] = fmaxf(a0.x + b0.x, 0.f); v[1] = fmaxf(a0.y + b0.y, 0.f);
                v[2] = fmaxf(a0.z + b0.z, 0.f); v[3] = fmaxf(a0.w + b0.w, 0.f);
                v[4] = fmaxf(a1.x + b1.x, 0.f); v[5] = fmaxf(a1.y + b1.y, 0.f);
                v[6] = fmaxf(a1.z + b1.z, 0.f); v[7] = fmaxf(a1.w + b1.w, 0.f);
                split8(v, vh, vl);
            } else {
                vh = *(const uint4*)&inh[(size_t)(node0 + row) * KT + k0 + cu * 8];
                vl = *(const uint4*)&inl[(size_t)(node0 + row) * KT + k0 + cu * 8];
            }
            *(uint4*)&Ah[row * SP + cu * 8] = vh;
            *(uint4*)&Al[row * SP + cu * 8] = vl;
        }
        __syncthreads();

        // ---- MMA over this chunk
#pragma unroll
        for (int ks = 0; ks < KC / 16; ks++) {
            const int kb = ks * 16 + (lane & 3) * 2;     // fragment k offset
            const int ra = mrow + (lane >> 2);           // fragment row base
            u32 ah[2][4], al[2][4];
#pragma unroll
            for (int mt = 0; mt < 2; mt++) {
                int r = ra + mt * 16;
                ah[mt][0] = *(const u32*)&Ah[r * SP + kb];
                ah[mt][1] = *(const u32*)&Ah[(r + 8) * SP + kb];
                ah[mt][2] = *(const u32*)&Ah[r * SP + kb + 8];
                ah[mt][3] = *(const u32*)&Ah[(r + 8) * SP + kb + 8];
                al[mt][0] = *(const u32*)&Al[r * SP + kb];
                al[mt][1] = *(const u32*)&Al[(r + 8) * SP + kb];
                al[mt][2] = *(const u32*)&Al[r * SP + kb + 8];
                al[mt][3] = *(const u32*)&Al[(r + 8) * SP + kb + 8];
            }
#pragma unroll
            for (int nt = 0; nt < 8; nt++) {
                int n = ncol + nt * 8 + (lane >> 2);
                u32 bh[2], bl[2];
                bh[0] = *(const u32*)&Wh[n * SP + kb];
                bh[1] = *(const u32*)&Wh[n * SP + kb + 8];
                bl[0] = *(const u32*)&Wl[n * SP + kb];
                bl[1] = *(const u32*)&Wl[n * SP + kb + 8];
#pragma unroll
                for (int mt = 0; mt < 2; mt++) {
                    mma16816(acc[mt][nt], ah[mt], bh);
                    mma16816(acc[mt][nt], ah[mt], bl);
                    mma16816(acc[mt][nt], al[mt], bh);
                }
            }
        }
    }

    // ---- epilogue: h = D, agg = D * dinv^2
#pragma unroll
    for (int mt = 0; mt < 2; mt++) {
        int r0 = node0 + mrow + mt * 16 + (lane >> 2);
        int r1 = r0 + 8;
        bool v0 = r0 < NN, v1 = r1 < NN;
        float d20 = 0.f, d21 = 0.f;
        if (v0) { float d = g_dinv[r0]; d20 = d * d; }
        if (v1) { float d = g_dinv[r1]; d21 = d * d; }
#pragma unroll
        for (int nt = 0; nt < 8; nt++) {
            int cc = ncol + nt * 8 + (lane & 3) * 2;
            if (v0) {
                float2 hv = make_float2(acc[mt][nt][0], acc[mt][nt][1]);
                *(float2*)&hout[(size_t)r0 * HH + cc] = hv;
                *(float2*)&agg[(size_t)r0 * HH + cc] = make_float2(hv.x * d20, hv.y * d20);
            }
            if (v1) {
                float2 hv = make_float2(acc[mt][nt][2], acc[mt][nt][3]);
                *(float2*)&hout[(size_t)r1 * HH + cc] = hv;
                *(float2*)&agg[(size_t)r1 * HH + cc] = make_float2(hv.x * d21, hv.y * d21);
            }
        }
    }
}

// ---------------- edge scatter: agg[dst] += h[src] * dinv[s]*dinv[d] --------
__global__ void __launch_bounds__(256) scatter_kernel(const int* __restrict__ src,
                                                      const int* __restrict__ dst) {
    int e = blockIdx.x * 8 + (threadIdx.x >> 5);
    if (e >= EE) return;
    int lane = threadIdx.x & 31;
    int s = __ldg(&src[e]);
    int d = __ldg(&dst[e]);
    float w = g_dinv[s] * g_dinv[d];
    float4 v = *(const float4*)&g_h[(size_t)s * HH + lane * 4];
    float4 m = make_float4(v.x * w, v.y * w, v.z * w, v.w * w);
    float* p = &g_agg[(size_t)d * HH + lane * 4];
    asm volatile("red.global.add.v4.f32 [%0], {%1, %2, %3, %4};"
                 :: "l"(p), "f"(m.x), "f"(m.y), "f"(m.z), "f"(m.w)
                 : "memory");
}

// ---------------- final: relu + bias + mean-pool into out -------------------
__global__ void epilogue_pool_kernel(const float* __restrict__ bias,
                                     const int* __restrict__ batch_idx,
                                     float* __restrict__ out) {
    int idx = blockIdx.x * blockDim.x + threadIdx.x;   // over N*32
    if (idx >= NN * 32) return;
    int n = idx >> 5;
    int c4 = (idx & 31) * 4;
    int g = __ldg(&batch_idx[n]);
    float w = g_invcnt[g];
    float4 a = *(const float4*)&g_agg[(size_t)n * HH + c4];
    float4 b = *(const float4*)&bias[c4];
    float4 r = make_float4(fmaxf(a.x + b.x, 0.f) * w, fmaxf(a.y + b.y, 0.f) * w,
                           fmaxf(a.z + b.z, 0.f) * w, fmaxf(a.w + b.w, 0.f) * w);
    float* p = &out[(size_t)g * HH + c4];
    asm volatile("red.global.add.v4.f32 [%0], {%1, %2, %3, %4};"
                 :: "l"(p), "f"(r.x), "f"(r.y), "f"(r.z), "f"(r.w)
                 : "memory");
}

// ---------------- launch ------------------------------------------------------
extern "C" void kernel_launch(void* const* d_in, const int* in_sizes, int n_in,
                              void* d_out, int out_size) {
    const float* x         = (const float*)d_in[0];
    const int*   edge      = (const int*)d_in[1];     // [2, E]
    const int*   batch_idx = (const int*)d_in[2];
    const float* W1        = (const float*)d_in[3];
    const float* b1        = (const float*)d_in[4];
    const float* W2        = (const float*)d_in[5];
    const float* b2        = (const float*)d_in[6];
    const float* W3        = (const float*)d_in[7];
    const float* b3        = (const float*)d_in[8];
    float* out = (float*)d_out;

    const int* src = edge;
    const int* dst = edge + EE;

    float *hptr, *aggptr;
    __nv_bfloat16 *x1h, *x1l, *w1h, *w1l, *w2h, *w2l, *w3h, *w3l;
    cudaGetSymbolAddress((void**)&hptr,   g_h);
    cudaGetSymbolAddress((void**)&aggptr, g_agg);
    cudaGetSymbolAddress((void**)&x1h, g_x1h);
    cudaGetSymbolAddress((void**)&x1l, g_x1l);
    cudaGetSymbolAddress((void**)&w1h, g_w1h);
    cudaGetSymbolAddress((void**)&w1l, g_w1l);
    cudaGetSymbolAddress((void**)&w2h, g_w2h);
    cudaGetSymbolAddress((void**)&w2l, g_w2l);
    cudaGetSymbolAddress((void**)&w3h, g_w3h);
    cudaGetSymbolAddress((void**)&w3l, g_w3l);

    // dynamic smem: 4 arrays of 128 * (KC+8) bf16
    const int SMEM_L1 = 4 * 128 * (32 + 8) * 2;   // 40960
    const int SMEM_L2 = 4 * 128 * (64 + 8) * 2;   // 73728
    cudaFuncSetAttribute(gemm_mma<32, 0>,  cudaFuncAttributeMaxDynamicSharedMemorySize, SMEM_L1);
    cudaFuncSetAttribute(gemm_mma<128, 1>, cudaFuncAttributeMaxDynamicSharedMemorySize, SMEM_L2);

    const int T = 256;
    init_kernel<<<(GG * HH + T - 1) / T, T>>>(out);
    count_kernel<<<(EE + T - 1) / T, T>>>(dst, batch_idx);
    finalize_kernel<<<(NN + T - 1) / T, T>>>();
    splitx_kernel<<<(NPAD * 4 + T - 1) / T, T>>>(x);
    prepw_kernel<<<(128 * 32 + T - 1) / T, T>>>(W1, DIN, 32, w1h, w1l);
    prepw_kernel<<<(128 * 128 + T - 1) / T, T>>>(W2, HH, 128, w2h, w2l);
    prepw_kernel<<<(128 * 128 + T - 1) / T, T>>>(W3, HH, 128, w3h, w3l);

    const int gemm_grid    = NPAD / 128;        // 1563
    const int scatter_grid = (EE + 7) / 8;      // 75000
    const int vec_grid     = (NN * 32 + T - 1) / T;

    // ---- layer 1 (pre-split bf16 input, K padded to 32)
    gemm_mma<32, 0><<<gemm_grid, T, SMEM_L1>>>(x1h, x1l, nullptr, nullptr, w1h, w1l, hptr, aggptr);
    scatter_kernel<<<scatter_grid, T>>>(src, dst);

    // ---- layer 2: A = relu(agg + b1) fused, K=128
    gemm_mma<128, 1><<<gemm_grid, T, SMEM_L2>>>(nullptr, nullptr, aggptr, b1, w2h, w2l, hptr, aggptr);
    scatter_kernel<<<scatter_grid, T>>>(src, dst);

    // ---- layer 3: A = relu(agg + b2) fused, K=128
    gemm_mma<128, 1><<<gemm_grid, T, SMEM_L2>>>(nullptr, nullptr, aggptr, b2, w3h, w3l, hptr, aggptr);
    scatter_kernel<<<scatter_grid, T>>>(src, dst);

    // ---- final: relu + b3 + mean-pool
    epilogue_pool_kernel<<<vec_grid, T>>>(b3, batch_idx, out);
}